// round 1
// baseline (speedup 1.0000x reference)
#include <cuda_runtime.h>
#include <cuda_bf16.h>
#include <cstddef>

// Problem constants
#define NB    4
#define TT_   64
#define LL    64
#define QCH   256
#define KVCH  64
#define GRP   4
#define PPG   16
#define PTOT  (NB*LL*LL)          // 16384 pixels
#define SCALE 0.25f               // 1/sqrt(PPG)

typedef unsigned long long ull;

// Scratch (device globals; no allocation allowed)
__device__ float g_qk[PTOT * 256];   // qk[p][g*64+e], scale folded in
__device__ float g_w [PTOT * 256];   // w [p][g*64+e]

// ---------- packed fp32x2 helpers (FFMA2: 2 FMAs/instr on sm_103a) ----------
__device__ __forceinline__ ull pack2(float lo, float hi) {
    ull r; asm("mov.b64 %0, {%1,%2};" : "=l"(r) : "f"(lo), "f"(hi)); return r;
}
__device__ __forceinline__ void ffma2(ull& d, ull a, ull b) {
    asm("fma.rn.f32x2 %0, %1, %2, %0;" : "+l"(d) : "l"(a), "l"(b));
}
__device__ __forceinline__ float2 unpack2(ull v) {
    float lo, hi; asm("mov.b64 {%0,%1}, %2;" : "=f"(lo), "=f"(hi) : "l"(v));
    float2 f; f.x = lo; f.y = hi; return f;
}

// =====================================================================
// Kernel 1: qk[p][g*64+e] = SCALE * sum_c (q[p]@Wq)[g*16+c] * Wk[e][g*16+c]
// Grid: 256 blocks x 256 threads, 64 rows (pixels) per block.
// =====================================================================
__global__ void __launch_bounds__(256) qk_kernel(const float* __restrict__ q,
                                                 const float* __restrict__ Wq,
                                                 const float* __restrict__ Wk) {
    extern __shared__ float sm[];
    float* sWq = sm;            // [256][64]
    float* sWk = sm + 16384;    // [64][64]
    float* sQ  = sm + 20480;    // [64][256]
    float* sQh = sm + 36864;    // [64][64]
    const int tid = threadIdx.x;
    const int rowBase = blockIdx.x * 64;

    {
        const float4* s0 = (const float4*)Wq;
        float4* d0 = (float4*)sWq;
        for (int i = tid; i < 4096; i += 256) d0[i] = s0[i];
        const float4* s1 = (const float4*)Wk;
        float4* d1 = (float4*)sWk;
        for (int i = tid; i < 1024; i += 256) d1[i] = s1[i];
        const float4* s2 = (const float4*)(q + (size_t)rowBase * 256);
        float4* d2 = (float4*)sQ;
        for (int i = tid; i < 4096; i += 256) d2[i] = s2[i];
    }
    __syncthreads();

    // Phase 1: qh[64][64] = Qtile @ Wq, thread tile 4x4, FFMA2 over col pairs
    {
        const int tr = (tid >> 4) * 4;
        const int tc = (tid & 15) * 4;
        ull acc[4][2];
#pragma unroll
        for (int i = 0; i < 4; i++) { acc[i][0] = 0ULL; acc[i][1] = 0ULL; }
        for (int r = 0; r < 256; r += 4) {
            ull wp[4][2];
#pragma unroll
            for (int kk = 0; kk < 4; kk++) {
                wp[kk][0] = *(const ull*)&sWq[(r + kk) * 64 + tc];
                wp[kk][1] = *(const ull*)&sWq[(r + kk) * 64 + tc + 2];
            }
#pragma unroll
            for (int ri = 0; ri < 4; ri++) {
                float4 qv = *(const float4*)&sQ[(tr + ri) * 256 + r];
                ull q0 = pack2(qv.x, qv.x), q1 = pack2(qv.y, qv.y);
                ull q2 = pack2(qv.z, qv.z), q3 = pack2(qv.w, qv.w);
                ffma2(acc[ri][0], q0, wp[0][0]); ffma2(acc[ri][1], q0, wp[0][1]);
                ffma2(acc[ri][0], q1, wp[1][0]); ffma2(acc[ri][1], q1, wp[1][1]);
                ffma2(acc[ri][0], q2, wp[2][0]); ffma2(acc[ri][1], q2, wp[2][1]);
                ffma2(acc[ri][0], q3, wp[3][0]); ffma2(acc[ri][1], q3, wp[3][1]);
            }
        }
#pragma unroll
        for (int ri = 0; ri < 4; ri++) {
            float2 a = unpack2(acc[ri][0]);
            float2 b = unpack2(acc[ri][1]);
            float4 o; o.x = a.x; o.y = a.y; o.z = b.x; o.w = b.y;
            *(float4*)&sQh[(tr + ri) * 64 + tc] = o;
        }
    }
    __syncthreads();

    // Phase 2: qk[row][g*64+e], K=16 per group; Wk row register-cached
    {
        const int e  = tid & 63;
        const int rq = tid >> 6;   // rows rq*16 .. rq*16+15
        ull wk[4][8];
#pragma unroll
        for (int g = 0; g < 4; g++)
#pragma unroll
            for (int c2 = 0; c2 < 8; c2++)
                wk[g][c2] = *(const ull*)&sWk[e * 64 + g * 16 + c2 * 2];
        for (int rr = 0; rr < 16; rr++) {
            const int row = rq * 16 + rr;
            const float* qh = &sQh[row * 64];
#pragma unroll
            for (int g = 0; g < 4; g++) {
                ull acc = 0ULL;
#pragma unroll
                for (int c2 = 0; c2 < 8; c2++)
                    ffma2(acc, *(const ull*)&qh[g * 16 + c2 * 2], wk[g][c2]);
                float2 a = unpack2(acc);
                g_qk[(size_t)(rowBase + row) * 256 + g * 64 + e] = SCALE * (a.x + a.y);
            }
        }
    }
}

// =====================================================================
// Kernel 2: per-pixel attention over T. One pixel per 128-thread block.
// scores -> softmax(T) -> w[g][e] = sum_t p[t][g]*kv[t][e]
// =====================================================================
__global__ void __launch_bounds__(128) attn_kernel(const float* __restrict__ kv) {
    __shared__ __align__(16) float kvs[64][68];     // kv tile, padded rows
    __shared__ __align__(16) float qks[256];
    __shared__ __align__(16) float sp[2][4][64];    // score partials (c-halves)
    __shared__ __align__(16) float ps[4][64];       // softmax probs [g][t]
    __shared__ __align__(16) float wsp[8][4][64];   // AV partials (t-slices)
    __shared__ float red[4][2];

    const int p   = blockIdx.x;
    const int tid = threadIdx.x;
    const int n   = p >> 12;
    const int ij  = p & 4095;
    const float* base = kv + ((size_t)n * 64 * 4096 + ij) * 64;

    if (tid < 64)
        ((float4*)qks)[tid] = ((const float4*)&g_qk[(size_t)p * 256])[tid];

    // Load kv tile: thread (t = tid>>1, half = tid&1) owns 32 channels.
    const int tt = tid >> 1;
    const int hh = tid & 1;
    float kreg[32];
    {
        const float4* src = (const float4*)(base + (size_t)tt * 262144 + hh * 32);
#pragma unroll
        for (int i = 0; i < 8; i++) {
            float4 v = src[i];
            *(float4*)&kvs[tt][hh * 32 + i * 4] = v;
            kreg[i * 4 + 0] = v.x; kreg[i * 4 + 1] = v.y;
            kreg[i * 4 + 2] = v.z; kreg[i * 4 + 3] = v.w;
        }
    }
    __syncthreads();

    // Scores (kv from registers; qk broadcast): partial over this thread's c-half
    {
        ull acc[4] = {0ULL, 0ULL, 0ULL, 0ULL};
        const int cbase = hh * 32;
#pragma unroll
        for (int j = 0; j < 32; j += 2) {
            ull k2 = pack2(kreg[j], kreg[j + 1]);
            ffma2(acc[0], k2, *(const ull*)&qks[0 * 64 + cbase + j]);
            ffma2(acc[1], k2, *(const ull*)&qks[1 * 64 + cbase + j]);
            ffma2(acc[2], k2, *(const ull*)&qks[2 * 64 + cbase + j]);
            ffma2(acc[3], k2, *(const ull*)&qks[3 * 64 + cbase + j]);
        }
#pragma unroll
        for (int g = 0; g < 4; g++) {
            float2 a = unpack2(acc[g]);
            sp[hh][g][tt] = a.x + a.y;
        }
    }
    __syncthreads();

    // Softmax over t, per group. Thread (t = tid&63, gh = tid>>6) owns 2 groups.
    const int t4 = tid & 63;
    const int gh = tid >> 6;
    const int g0 = gh * 2, g1 = gh * 2 + 1;
    {
        float s0 = sp[0][g0][t4] + sp[1][g0][t4];
        float s1 = sp[0][g1][t4] + sp[1][g1][t4];
        float m0 = s0, m1 = s1;
#pragma unroll
        for (int o = 16; o > 0; o >>= 1) {
            m0 = fmaxf(m0, __shfl_xor_sync(0xffffffffu, m0, o));
            m1 = fmaxf(m1, __shfl_xor_sync(0xffffffffu, m1, o));
        }
        const int w = tid >> 5;
        if ((tid & 31) == 0) { red[w][0] = m0; red[w][1] = m1; }
        __syncthreads();
        const int wb = gh * 2;
        m0 = fmaxf(red[wb][0], red[wb + 1][0]);
        m1 = fmaxf(red[wb][1], red[wb + 1][1]);
        float e0 = __expf(s0 - m0);
        float e1 = __expf(s1 - m1);
        float q0 = e0, q1 = e1;
#pragma unroll
        for (int o = 16; o > 0; o >>= 1) {
            q0 += __shfl_xor_sync(0xffffffffu, q0, o);
            q1 += __shfl_xor_sync(0xffffffffu, q1, o);
        }
        __syncthreads();   // everyone done reading max partials
        if ((tid & 31) == 0) { red[w][0] = q0; red[w][1] = q1; }
        __syncthreads();
        float sum0 = red[wb][0] + red[wb + 1][0];
        float sum1 = red[wb][1] + red[wb + 1][1];
        ps[g0][t4] = e0 / sum0;
        ps[g1][t4] = e1 / sum1;
    }
    __syncthreads();

    // AV: w[g][e] = sum_t p[t][g]*kv[t][e]. Thread (e4 = tid&15, slice = tid>>4)
    {
        const int e4  = tid & 15;
        const int th2 = tid >> 4;      // 8 t-slices of 8
        ull acc[4][2];
#pragma unroll
        for (int g = 0; g < 4; g++) { acc[g][0] = 0ULL; acc[g][1] = 0ULL; }
#pragma unroll
        for (int j = 0; j < 8; j++) {
            const int t = th2 * 8 + j;
            ull k01 = *(const ull*)&kvs[t][e4 * 4];
            ull k23 = *(const ull*)&kvs[t][e4 * 4 + 2];
#pragma unroll
            for (int g = 0; g < 4; g++) {
                float pv = ps[g][t];
                ull pp = pack2(pv, pv);
                ffma2(acc[g][0], pp, k01);
                ffma2(acc[g][1], pp, k23);
            }
        }
#pragma unroll
        for (int g = 0; g < 4; g++) {
            float2 a = unpack2(acc[g][0]);
            float2 b = unpack2(acc[g][1]);
            float4 o; o.x = a.x; o.y = a.y; o.z = b.x; o.w = b.y;
            *(float4*)&wsp[th2][g][e4 * 4] = o;
        }
    }
    __syncthreads();

    // Reduce 8 t-slices, store w to global
#pragma unroll
    for (int r = 0; r < 2; r++) {
        const int o = tid + r * 128;
        const int g = o >> 6, e = o & 63;
        float s = 0.f;
#pragma unroll
        for (int sl = 0; sl < 8; sl++) s += wsp[sl][g][e];
        g_w[(size_t)p * 256 + o] = s;
    }
}

// =====================================================================
// Kernel 3: x[p] = per-group w@Wv ; out[p] = x@Wout + b
// Grid: 256 blocks x 256 threads, 64 rows per block.
// =====================================================================
__global__ void __launch_bounds__(256) out_kernel(const float* __restrict__ Wv,
                                                  const float* __restrict__ Wout,
                                                  const float* __restrict__ bias,
                                                  float* __restrict__ out) {
    extern __shared__ float sm[];
    float* sWv   = sm;            // [64][64]
    float* sWout = sm + 4096;     // [64][256]
    float* sW    = sm + 20480;    // [64][256]
    float* sX    = sm + 36864;    // [64][64]
    const int tid = threadIdx.x;
    const int rowBase = blockIdx.x * 64;

    {
        const float4* s0 = (const float4*)Wv;
        float4* d0 = (float4*)sWv;
        for (int i = tid; i < 1024; i += 256) d0[i] = s0[i];
        const float4* s1 = (const float4*)Wout;
        float4* d1 = (float4*)sWout;
        for (int i = tid; i < 4096; i += 256) d1[i] = s1[i];
        const float4* s2 = (const float4*)&g_w[(size_t)rowBase * 256];
        float4* d2 = (float4*)sW;
        for (int i = tid; i < 4096; i += 256) d2[i] = s2[i];
    }
    __syncthreads();

    // Phase 1: x[row][k] = sum_e w[row][g*64+e] * Wv[e][k],  g = k/16
    {
        const int tr = (tid >> 4) * 4;
        const int tc = (tid & 15) * 4;
        const int g  = tc >> 4;
        ull acc[4][2];
#pragma unroll
        for (int i = 0; i < 4; i++) { acc[i][0] = 0ULL; acc[i][1] = 0ULL; }
        for (int e = 0; e < 64; e++) {
            ull w0 = *(const ull*)&sWv[e * 64 + tc];
            ull w1 = *(const ull*)&sWv[e * 64 + tc + 2];
#pragma unroll
            for (int ri = 0; ri < 4; ri++) {
                float wv = sW[(tr + ri) * 256 + g * 64 + e];
                ull ww = pack2(wv, wv);
                ffma2(acc[ri][0], ww, w0);
                ffma2(acc[ri][1], ww, w1);
            }
        }
#pragma unroll
        for (int ri = 0; ri < 4; ri++) {
            float2 a = unpack2(acc[ri][0]);
            float2 b = unpack2(acc[ri][1]);
            float4 o; o.x = a.x; o.y = a.y; o.z = b.x; o.w = b.y;
            *(float4*)&sX[(tr + ri) * 64 + tc] = o;
        }
    }
    __syncthreads();

    // Phase 2: out[row][d] = b[d] + sum_k x[row][k]*Wout[k][d]
    {
        const int rt = tid >> 4;     // rows rt*4 .. rt*4+3
        const int dt = tid & 15;     // cols dt*16 .. dt*16+15
        ull acc[4][8];
#pragma unroll
        for (int i = 0; i < 4; i++)
#pragma unroll
            for (int j = 0; j < 8; j++) acc[i][j] = 0ULL;
        for (int k = 0; k < 64; k++) {
            ull wd[8];
#pragma unroll
            for (int j = 0; j < 8; j++)
                wd[j] = *(const ull*)&sWout[k * 256 + dt * 16 + j * 2];
#pragma unroll
            for (int ri = 0; ri < 4; ri++) {
                float xv = sX[(rt * 4 + ri) * 64 + k];
                ull xx = pack2(xv, xv);
#pragma unroll
                for (int j = 0; j < 8; j++) ffma2(acc[ri][j], xx, wd[j]);
            }
        }
        float bvals[16];
#pragma unroll
        for (int j = 0; j < 4; j++)
            *(float4*)&bvals[j * 4] = ((const float4*)bias)[dt * 4 + j];
#pragma unroll
        for (int ri = 0; ri < 4; ri++) {
            const int row = rowBase + rt * 4 + ri;
            float o[16];
#pragma unroll
            for (int j = 0; j < 8; j++) {
                float2 a = unpack2(acc[ri][j]);
                o[2 * j]     = a.x + bvals[2 * j];
                o[2 * j + 1] = a.y + bvals[2 * j + 1];
            }
#pragma unroll
            for (int j = 0; j < 4; j++)
                *(float4*)&out[(size_t)row * 256 + dt * 16 + j * 4] =
                    *(float4*)&o[j * 4];
        }
    }
}

extern "C" void kernel_launch(void* const* d_in, const int* in_sizes, int n_in,
                              void* d_out, int out_size) {
    const float* q    = (const float*)d_in[0];
    const float* kv   = (const float*)d_in[1];
    const float* Wq   = (const float*)d_in[2];
    const float* Wk   = (const float*)d_in[3];
    const float* Wv   = (const float*)d_in[4];
    const float* Wout = (const float*)d_in[5];
    const float* bias = (const float*)d_in[6];
    float* out = (float*)d_out;

    cudaFuncSetAttribute(qk_kernel,  cudaFuncAttributeMaxDynamicSharedMemorySize, 163840);
    cudaFuncSetAttribute(out_kernel, cudaFuncAttributeMaxDynamicSharedMemorySize, 163840);

    qk_kernel<<<PTOT / 64, 256, 163840>>>(q, Wq, Wk);
    attn_kernel<<<PTOT, 128>>>(kv);
    out_kernel<<<PTOT / 64, 256, 163840>>>(Wv, Wout, bias, out);
}

// round 3
// speedup vs baseline: 1.7717x; 1.7717x over previous
#include <cuda_runtime.h>
#include <cuda_bf16.h>
#include <cstddef>

// Problem constants
#define NB    4
#define TT_   64
#define LL    64
#define QCH   256
#define KVCH  64
#define GRP   4
#define PPG   16
#define PTOT  (NB*LL*LL)          // 16384 pixels
#define SCALE 0.25f               // 1/sqrt(PPG)

typedef unsigned long long ull;

// Scratch (device globals; no allocation allowed)
__device__ float g_qk[PTOT * 256];   // qk[p][g*64+e], scale folded in
__device__ float g_w [PTOT * 256];   // w [p][g*64+e]

// ---------- packed fp32x2 helpers (FFMA2) ----------
__device__ __forceinline__ ull pack2(float lo, float hi) {
    ull r; asm("mov.b64 %0, {%1,%2};" : "=l"(r) : "f"(lo), "f"(hi)); return r;
}
__device__ __forceinline__ void ffma2(ull& d, ull a, ull b) {
    asm("fma.rn.f32x2 %0, %1, %2, %0;" : "+l"(d) : "l"(a), "l"(b));
}
__device__ __forceinline__ float2 unpack2(ull v) {
    float lo, hi; asm("mov.b64 {%0,%1}, %2;" : "=f"(lo), "=f"(hi) : "l"(v));
    float2 f; f.x = lo; f.y = hi; return f;
}

// =====================================================================
// Kernel 1: qk[p][g*64+e] = SCALE * sum_c (q[p]@Wq)[g*16+c] * Wk[e][g*16+c]
// 256 blocks x 256 threads, 64 rows per block. K streamed in 4 chunks of 64
// so smem = 66KB -> 3 CTAs/SM.
// =====================================================================
__global__ void __launch_bounds__(256) qk_kernel(const float* __restrict__ q,
                                                 const float* __restrict__ Wq,
                                                 const float* __restrict__ Wk) {
    extern __shared__ float sm[];
    float* sWq = sm;                  // [64][64] chunk of Wq rows
    float* sQ  = sm + 4096;           // [64][64] chunk of q cols
    float* sWk = sm + 8192;           // [64][66] padded (stride 66)
    float* sQh = sm + 8192 + 4224;    // [64][64]
    const int tid = threadIdx.x;
    const int rowBase = blockIdx.x * 64;

    // Load Wk once, padded rows (stride 66 -> conflict-free phase-2 reads)
    for (int i = tid; i < 2048; i += 256) {
        const int e = i >> 5, cp = i & 31;
        *(float2*)&sWk[e * 66 + cp * 2] = ((const float2*)Wk)[i];
    }

    const int tr = (tid >> 4) * 4;
    const int tc = (tid & 15) * 4;
    const int lrow = tid >> 4;   // 0..15
    const int lf   = tid & 15;

    ull acc[4][2];
#pragma unroll
    for (int i = 0; i < 4; i++) { acc[i][0] = 0ULL; acc[i][1] = 0ULL; }

    for (int c = 0; c < 4; c++) {
        __syncthreads();   // previous chunk fully consumed (also orders sWk init)
        // Wq chunk rows c*64..c*64+63: contiguous 16KB
        {
            const float4* src = (const float4*)(Wq + c * 4096);
            for (int i = tid; i < 1024; i += 256) ((float4*)sWq)[i] = src[i];
        }
        // q chunk: 2 rows per warp-instr, 16 lanes contiguous per row
#pragma unroll
        for (int j = 0; j < 4; j++) {
            const int row = lrow + j * 16;
            ((float4*)sQ)[row * 16 + lf] =
                ((const float4*)(q + (size_t)(rowBase + row) * 256 + c * 64))[lf];
        }
        __syncthreads();

        for (int r = 0; r < 64; r += 4) {
            ull w01[4], w23[4];
#pragma unroll
            for (int kk = 0; kk < 4; kk++) {
                float4 wp = *(const float4*)&sWq[(r + kk) * 64 + tc];
                w01[kk] = pack2(wp.x, wp.y);
                w23[kk] = pack2(wp.z, wp.w);
            }
#pragma unroll
            for (int ri = 0; ri < 4; ri++) {
                float4 qv = *(const float4*)&sQ[(tr + ri) * 64 + r];
                ull q0 = pack2(qv.x, qv.x), q1 = pack2(qv.y, qv.y);
                ull q2 = pack2(qv.z, qv.z), q3 = pack2(qv.w, qv.w);
                ffma2(acc[ri][0], q0, w01[0]); ffma2(acc[ri][1], q0, w23[0]);
                ffma2(acc[ri][0], q1, w01[1]); ffma2(acc[ri][1], q1, w23[1]);
                ffma2(acc[ri][0], q2, w01[2]); ffma2(acc[ri][1], q2, w23[2]);
                ffma2(acc[ri][0], q3, w01[3]); ffma2(acc[ri][1], q3, w23[3]);
            }
        }
    }

#pragma unroll
    for (int ri = 0; ri < 4; ri++) {
        float2 a = unpack2(acc[ri][0]);
        float2 b = unpack2(acc[ri][1]);
        float4 o; o.x = a.x; o.y = a.y; o.z = b.x; o.w = b.y;
        *(float4*)&sQh[(tr + ri) * 64 + tc] = o;
    }
    __syncthreads();

    // Phase 2: qk[row][g*64+e]; Wk row cached in regs, qh broadcast reads
    {
        const int e  = tid & 63;
        const int rq = tid >> 6;
        ull wk[4][8];
#pragma unroll
        for (int g = 0; g < 4; g++)
#pragma unroll
            for (int c2 = 0; c2 < 8; c2++)
                wk[g][c2] = *(const ull*)&sWk[e * 66 + g * 16 + c2 * 2];
        for (int rr = 0; rr < 16; rr++) {
            const int row = rq * 16 + rr;
            const float* qh = &sQh[row * 64];
            float* dst = &g_qk[(size_t)(rowBase + row) * 256 + e];
#pragma unroll
            for (int g = 0; g < 4; g++) {
                ull a = 0ULL;
#pragma unroll
                for (int c2 = 0; c2 < 8; c2++)
                    ffma2(a, *(const ull*)&qh[g * 16 + c2 * 2], wk[g][c2]);
                float2 v = unpack2(a);
                dst[g * 64] = SCALE * (v.x + v.y);
            }
        }
    }
}

// =====================================================================
// Kernel 2: per-pixel attention over T. One pixel per 128-thread block.
// Coalesced kv load (2 t-rows per warp-instr); AV from registers.
// =====================================================================
__global__ void __launch_bounds__(128) attn_kernel(const float* __restrict__ kv) {
    __shared__ __align__(16) float kvs[64 * 68];   // pad 68 (= 4 mod 32)
    __shared__ __align__(16) float qks[256];
    __shared__ __align__(16) float ps[4][64];
    __shared__ __align__(16) float wsp[8][256];
    __shared__ float red[4][2];

    const int p   = blockIdx.x;
    const int tid = threadIdx.x;
    const float* base = kv + (size_t)(p >> 12) * (64u * 4096u * 64u)
                           + (size_t)(p & 4095) * 64;

    if (tid < 64)
        ((float4*)qks)[tid] = ((const float4*)(g_qk + (size_t)p * 256))[tid];

    // Load: thread owns channels 4*f4..+3 for t = sl + 8k (k=0..7).
    // Per warp-instr: 2 rows x 256B contiguous -> 4 cache lines (optimal).
    const int f4 = tid & 15;
    const int sl = tid >> 4;
    float4 kreg[8];
#pragma unroll
    for (int k = 0; k < 8; k++) {
        const int t = sl + k * 8;
        float4 v = *(const float4*)(base + (size_t)t * 262144 + f4 * 4);
        kreg[k] = v;
        *(float4*)&kvs[t * 68 + f4 * 4] = v;
    }
    __syncthreads();

    // Scores + softmax, fused: thread = (t = tid&63, group pair gh = tid>>6)
    const int t  = tid & 63;
    const int gh = tid >> 6;
    {
        const float* krow = &kvs[t * 68];
        const float* qa = &qks[(2 * gh) * 64];
        const float* qb = qa + 64;
        float a0 = 0.f, a1 = 0.f, b0 = 0.f, b1 = 0.f;
#pragma unroll
        for (int i = 0; i < 8; i++) {
            float4 k0 = *(const float4*)&krow[i * 8];
            float4 k1 = *(const float4*)&krow[i * 8 + 4];
            float4 u0 = *(const float4*)&qa[i * 8];
            float4 u1 = *(const float4*)&qa[i * 8 + 4];
            float4 v0 = *(const float4*)&qb[i * 8];
            float4 v1 = *(const float4*)&qb[i * 8 + 4];
            a0 = fmaf(k0.x, u0.x, a0); a0 = fmaf(k0.y, u0.y, a0);
            a0 = fmaf(k0.z, u0.z, a0); a0 = fmaf(k0.w, u0.w, a0);
            a1 = fmaf(k1.x, u1.x, a1); a1 = fmaf(k1.y, u1.y, a1);
            a1 = fmaf(k1.z, u1.z, a1); a1 = fmaf(k1.w, u1.w, a1);
            b0 = fmaf(k0.x, v0.x, b0); b0 = fmaf(k0.y, v0.y, b0);
            b0 = fmaf(k0.z, v0.z, b0); b0 = fmaf(k0.w, v0.w, b0);
            b1 = fmaf(k1.x, v1.x, b1); b1 = fmaf(k1.y, v1.y, b1);
            b1 = fmaf(k1.z, v1.z, b1); b1 = fmaf(k1.w, v1.w, b1);
        }
        float s0 = a0 + a1, s1 = b0 + b1;

        float m0 = s0, m1 = s1;
#pragma unroll
        for (int o = 16; o > 0; o >>= 1) {
            m0 = fmaxf(m0, __shfl_xor_sync(0xffffffffu, m0, o));
            m1 = fmaxf(m1, __shfl_xor_sync(0xffffffffu, m1, o));
        }
        const int w = tid >> 5;
        if ((tid & 31) == 0) { red[w][0] = m0; red[w][1] = m1; }
        __syncthreads();
        const int wb = gh * 2;
        m0 = fmaxf(red[wb][0], red[wb + 1][0]);
        m1 = fmaxf(red[wb][1], red[wb + 1][1]);
        float e0 = __expf(s0 - m0);
        float e1 = __expf(s1 - m1);
        float q0 = e0, q1 = e1;
#pragma unroll
        for (int o = 16; o > 0; o >>= 1) {
            q0 += __shfl_xor_sync(0xffffffffu, q0, o);
            q1 += __shfl_xor_sync(0xffffffffu, q1, o);
        }
        __syncthreads();   // all done reading max partials
        if ((tid & 31) == 0) { red[w][0] = q0; red[w][1] = q1; }
        __syncthreads();
        float sum0 = red[wb][0] + red[wb + 1][0];
        float sum1 = red[wb][1] + red[wb + 1][1];
        ps[2 * gh][t]     = e0 / sum0;
        ps[2 * gh + 1][t] = e1 / sum1;
    }
    __syncthreads();

    // AV from registers: acc[g] over this thread's 8 t's, 4 channels
    {
        ull acc[4][2];
#pragma unroll
        for (int g = 0; g < 4; g++) { acc[g][0] = 0ULL; acc[g][1] = 0ULL; }
#pragma unroll
        for (int k = 0; k < 8; k++) {
            const int tt = sl + k * 8;
            ull k01 = pack2(kreg[k].x, kreg[k].y);
            ull k23 = pack2(kreg[k].z, kreg[k].w);
#pragma unroll
            for (int g = 0; g < 4; g++) {
                float pv = ps[g][tt];
                ull pp = pack2(pv, pv);
                ffma2(acc[g][0], pp, k01);
                ffma2(acc[g][1], pp, k23);
            }
        }
#pragma unroll
        for (int g = 0; g < 4; g++) {
            float2 a = unpack2(acc[g][0]);
            float2 b = unpack2(acc[g][1]);
            float4 o; o.x = a.x; o.y = a.y; o.z = b.x; o.w = b.y;
            *(float4*)&wsp[sl][g * 64 + f4 * 4] = o;
        }
    }
    __syncthreads();

    // Reduce 8 t-slices, store w (float2 per thread)
    {
        const int o = tid * 2;
        float sx = 0.f, sy = 0.f;
#pragma unroll
        for (int slc = 0; slc < 8; slc++) {
            float2 v = *(const float2*)&wsp[slc][o];
            sx += v.x; sy += v.y;
        }
        float2 r; r.x = sx; r.y = sy;
        *(float2*)&g_w[(size_t)p * 256 + o] = r;
    }
}

// =====================================================================
// Kernel 3: x[p] = per-group w@Wv ; out[p] = x@Wout + b
// 256 blocks x 256 threads, 64 rows per block. 96KB smem -> 2 CTAs/SM.
// sBig shared between w-tile (phase1) and Wout (phase2).
// =====================================================================
__global__ void __launch_bounds__(256) out_kernel(const float* __restrict__ Wv,
                                                  const float* __restrict__ Wout,
                                                  const float* __restrict__ bias,
                                                  float* __restrict__ out) {
    extern __shared__ float sm[];
    float* sBig = sm;                 // [64][256]: w tile, then Wout
    float* sWv  = sm + 16384;         // [64][64]
    float* sX   = sm + 16384 + 4096;  // [64][64]
    const int tid = threadIdx.x;
    const int rowBase = blockIdx.x * 64;

    for (int i = tid; i < 1024; i += 256) ((float4*)sWv)[i] = ((const float4*)Wv)[i];
    {
        const float4* src = (const float4*)(g_w + (size_t)rowBase * 256);
        for (int i = tid; i < 4096; i += 256) ((float4*)sBig)[i] = src[i];
    }
    __syncthreads();

    // Phase 1: x[row][k] = sum_e w[row][g*64+e] * Wv[e][k], g = k>>4
    {
        const int tr = (tid >> 4) * 4;
        const int tc = (tid & 15) * 4;
        const int g  = tc >> 4;
        ull acc[4][2];
#pragma unroll
        for (int i = 0; i < 4; i++) { acc[i][0] = 0ULL; acc[i][1] = 0ULL; }
        for (int e = 0; e < 64; e++) {
            float4 wv = *(const float4*)&sWv[e * 64 + tc];
            ull w01 = pack2(wv.x, wv.y), w23 = pack2(wv.z, wv.w);
#pragma unroll
            for (int ri = 0; ri < 4; ri++) {
                float x = sBig[(tr + ri) * 256 + g * 64 + e];
                ull xx = pack2(x, x);
                ffma2(acc[ri][0], xx, w01);
                ffma2(acc[ri][1], xx, w23);
            }
        }
#pragma unroll
        for (int ri = 0; ri < 4; ri++) {
            float2 a = unpack2(acc[ri][0]);
            float2 b = unpack2(acc[ri][1]);
            float4 o; o.x = a.x; o.y = a.y; o.z = b.x; o.w = b.y;
            *(float4*)&sX[(tr + ri) * 64 + tc] = o;
        }
    }
    __syncthreads();

    // Reload sBig with Wout
    for (int i = tid; i < 4096; i += 256) ((float4*)sBig)[i] = ((const float4*)Wout)[i];
    __syncthreads();

    // Phase 2: out[row][d] = b[d] + sum_k x[row][k]*Wout[k][d]
    // thread = (rg = tid>>6 -> 16 rows, c4 = tid&63 -> 4 cols); conflict-free
    {
        const int rg = tid >> 6;
        const int c4 = tid & 63;
        ull acc[16][2];
#pragma unroll
        for (int i = 0; i < 16; i++) { acc[i][0] = 0ULL; acc[i][1] = 0ULL; }
        for (int k = 0; k < 64; k++) {
            float4 wd = *(const float4*)&sBig[k * 256 + c4 * 4];
            ull w01 = pack2(wd.x, wd.y), w23 = pack2(wd.z, wd.w);
            const float* xcol = &sX[rg * 16 * 64 + k];
#pragma unroll
            for (int rr = 0; rr < 16; rr++) {
                float xv = xcol[rr * 64];
                ull xx = pack2(xv, xv);
                ffma2(acc[rr][0], xx, w01);
                ffma2(acc[rr][1], xx, w23);
            }
        }
        float4 bv = ((const float4*)bias)[c4];
#pragma unroll
        for (int rr = 0; rr < 16; rr++) {
            float2 a = unpack2(acc[rr][0]);
            float2 b = unpack2(acc[rr][1]);
            float4 o;
            o.x = a.x + bv.x; o.y = a.y + bv.y;
            o.z = b.x + bv.z; o.w = b.y + bv.w;
            *(float4*)&out[(size_t)(rowBase + rg * 16 + rr) * 256 + c4 * 4] = o;
        }
    }
}

extern "C" void kernel_launch(void* const* d_in, const int* in_sizes, int n_in,
                              void* d_out, int out_size) {
    const float* q    = (const float*)d_in[0];
    const float* kv   = (const float*)d_in[1];
    const float* Wq   = (const float*)d_in[2];
    const float* Wk   = (const float*)d_in[3];
    const float* Wv   = (const float*)d_in[4];
    const float* Wout = (const float*)d_in[5];
    const float* bias = (const float*)d_in[6];
    float* out = (float*)d_out;

    cudaFuncSetAttribute(qk_kernel,  cudaFuncAttributeMaxDynamicSharedMemorySize, 66048);
    cudaFuncSetAttribute(out_kernel, cudaFuncAttributeMaxDynamicSharedMemorySize, 98304);

    qk_kernel<<<PTOT / 64, 256, 66048>>>(q, Wq, Wk);
    attn_kernel<<<PTOT, 128>>>(kv);
    out_kernel<<<PTOT / 64, 256, 98304>>>(Wv, Wout, bias, out);
}

// round 4
// speedup vs baseline: 1.8265x; 1.0309x over previous
#include <cuda_runtime.h>
#include <cuda_bf16.h>
#include <cstddef>

// Problem constants
#define NB    4
#define TT_   64
#define LL    64
#define QCH   256
#define KVCH  64
#define GRP   4
#define PPG   16
#define PTOT  (NB*LL*LL)          // 16384 pixels
#define SCALE 0.25f               // 1/sqrt(PPG)

typedef unsigned long long ull;

// Scratch (device globals; no allocation allowed)
__device__ float g_qk[PTOT * 256];   // qk[p][g*64+e], scale folded in
__device__ float g_w [PTOT * 256];   // w [p][g*64+e]

// ---------- packed fp32x2 helpers (FFMA2) ----------
__device__ __forceinline__ ull pack2(float lo, float hi) {
    ull r; asm("mov.b64 %0, {%1,%2};" : "=l"(r) : "f"(lo), "f"(hi)); return r;
}
__device__ __forceinline__ void ffma2(ull& d, ull a, ull b) {
    asm("fma.rn.f32x2 %0, %1, %2, %0;" : "+l"(d) : "l"(a), "l"(b));
}
__device__ __forceinline__ void fadd2(ull& d, ull a) {
    asm("add.rn.f32x2 %0, %0, %1;" : "+l"(d) : "l"(a));
}
__device__ __forceinline__ float2 unpack2(ull v) {
    float lo, hi; asm("mov.b64 {%0,%1}, %2;" : "=f"(lo), "=f"(hi) : "l"(v));
    float2 f; f.x = lo; f.y = hi; return f;
}

// =====================================================================
// Kernel 1: qk[p][g*64+e] = SCALE * sum_c (q[p]@Wq)[g*16+c] * Wk[e][g*16+c]
// 256 blocks x 256 threads, 64 rows per block. smem 49.6KB, 3 CTAs/SM.
// =====================================================================
__global__ void __launch_bounds__(256, 3) qk_kernel(const float* __restrict__ q,
                                                    const float* __restrict__ Wq,
                                                    const float* __restrict__ Wk) {
    extern __shared__ float sm[];
    float* sWq = sm;                  // [64][64] chunk of Wq rows (later: sQh)
    float* sQ  = sm + 4096;           // [64][64] chunk of q cols
    float* sWk = sm + 8192;           // [64][66] padded (stride 66)
    float* sQh = sm;                  // aliases sWq after chunk loop
    const int tid = threadIdx.x;
    const int rowBase = blockIdx.x * 64;

    // Load Wk once, padded rows (stride 66 -> conflict-free phase-2 reads)
    for (int i = tid; i < 2048; i += 256) {
        const int e = i >> 5, cp = i & 31;
        *(float2*)&sWk[e * 66 + cp * 2] = ((const float2*)Wk)[i];
    }

    const int tr = (tid >> 4) * 4;
    const int tc = (tid & 15) * 4;
    const int lrow = tid >> 4;   // 0..15
    const int lf   = tid & 15;

    ull acc[4][2];
#pragma unroll
    for (int i = 0; i < 4; i++) { acc[i][0] = 0ULL; acc[i][1] = 0ULL; }

    for (int c = 0; c < 4; c++) {
        __syncthreads();   // previous chunk fully consumed (also orders sWk init)
        {
            const float4* src = (const float4*)(Wq + c * 4096);
            for (int i = tid; i < 1024; i += 256) ((float4*)sWq)[i] = src[i];
        }
#pragma unroll
        for (int j = 0; j < 4; j++) {
            const int row = lrow + j * 16;
            ((float4*)sQ)[row * 16 + lf] =
                ((const float4*)(q + (size_t)(rowBase + row) * 256 + c * 64))[lf];
        }
        __syncthreads();

        for (int r = 0; r < 64; r += 4) {
            ull w01[4], w23[4];
#pragma unroll
            for (int kk = 0; kk < 4; kk++) {
                float4 wp = *(const float4*)&sWq[(r + kk) * 64 + tc];
                w01[kk] = pack2(wp.x, wp.y);
                w23[kk] = pack2(wp.z, wp.w);
            }
#pragma unroll
            for (int ri = 0; ri < 4; ri++) {
                float4 qv = *(const float4*)&sQ[(tr + ri) * 64 + r];
                ull q0 = pack2(qv.x, qv.x), q1 = pack2(qv.y, qv.y);
                ull q2 = pack2(qv.z, qv.z), q3 = pack2(qv.w, qv.w);
                ffma2(acc[ri][0], q0, w01[0]); ffma2(acc[ri][1], q0, w23[0]);
                ffma2(acc[ri][0], q1, w01[1]); ffma2(acc[ri][1], q1, w23[1]);
                ffma2(acc[ri][0], q2, w01[2]); ffma2(acc[ri][1], q2, w23[2]);
                ffma2(acc[ri][0], q3, w01[3]); ffma2(acc[ri][1], q3, w23[3]);
            }
        }
    }

    __syncthreads();   // all reads of sWq (chunk 3) done before aliasing as sQh
#pragma unroll
    for (int ri = 0; ri < 4; ri++) {
        float2 a = unpack2(acc[ri][0]);
        float2 b = unpack2(acc[ri][1]);
        float4 o; o.x = a.x; o.y = a.y; o.z = b.x; o.w = b.y;
        *(float4*)&sQh[(tr + ri) * 64 + tc] = o;
    }
    __syncthreads();

    // Phase 2: qk[row][g*64+e]; 2 groups per pass (32 wk regs, fits 85-reg cap)
    {
        const int e  = tid & 63;
        const int rq = tid >> 6;
#pragma unroll
        for (int gp = 0; gp < 2; gp++) {
            ull wk[2][8];
#pragma unroll
            for (int gg = 0; gg < 2; gg++)
#pragma unroll
                for (int c2 = 0; c2 < 8; c2++)
                    wk[gg][c2] = *(const ull*)&sWk[e * 66 + (gp * 2 + gg) * 16 + c2 * 2];
            for (int rr = 0; rr < 16; rr++) {
                const int row = rq * 16 + rr;
                const float* qh = &sQh[row * 64];
                float* dst = &g_qk[(size_t)(rowBase + row) * 256 + e];
#pragma unroll
                for (int gg = 0; gg < 2; gg++) {
                    const int g = gp * 2 + gg;
                    ull a = 0ULL;
#pragma unroll
                    for (int c2 = 0; c2 < 8; c2++)
                        ffma2(a, *(const ull*)&qh[g * 16 + c2 * 2], wk[gg][c2]);
                    float2 v = unpack2(a);
                    dst[g * 64] = SCALE * (v.x + v.y);
                }
            }
        }
    }
}

// =====================================================================
// Kernel 2: per-pixel attention over T. One pixel per 128-thread block.
// Coalesced kv load; FFMA2 scores; AV from registers; shfl-halved reduce.
// =====================================================================
__global__ void __launch_bounds__(128) attn_kernel(const float* __restrict__ kv) {
    __shared__ __align__(16) float kvs[64 * 68];   // pad 68 (= 4 mod 32)
    __shared__ __align__(16) float qks[256];
    __shared__ __align__(16) float ps[4][64];
    __shared__ __align__(16) float wsp[4][256];
    __shared__ float red[4][2];

    const int p   = blockIdx.x;
    const int tid = threadIdx.x;
    const float* base = kv + (size_t)(p >> 12) * (64u * 4096u * 64u)
                           + (size_t)(p & 4095) * 64;

    if (tid < 64)
        ((float4*)qks)[tid] = ((const float4*)(g_qk + (size_t)p * 256))[tid];

    // Load: thread owns channels 4*f4..+3 for t = sl + 8k (k=0..7).
    const int f4 = tid & 15;
    const int sl = tid >> 4;
    float4 kreg[8];
#pragma unroll
    for (int k = 0; k < 8; k++) {
        const int t = sl + k * 8;
        float4 v = *(const float4*)(base + (size_t)t * 262144 + f4 * 4);
        kreg[k] = v;
        *(float4*)&kvs[t * 68 + f4 * 4] = v;
    }
    __syncthreads();

    // Scores (FFMA2) + softmax: thread = (t = tid&63, group pair gh = tid>>6)
    const int t  = tid & 63;
    const int gh = tid >> 6;
    {
        const float* krow = &kvs[t * 68];
        const float* qa = &qks[(2 * gh) * 64];
        const float* qb = qa + 64;
        ull aA0 = 0ULL, aA1 = 0ULL, aB0 = 0ULL, aB1 = 0ULL;
#pragma unroll
        for (int i = 0; i < 8; i++) {
            float4 k0 = *(const float4*)&krow[i * 8];
            float4 k1 = *(const float4*)&krow[i * 8 + 4];
            float4 u0 = *(const float4*)&qa[i * 8];
            float4 u1 = *(const float4*)&qa[i * 8 + 4];
            float4 v0 = *(const float4*)&qb[i * 8];
            float4 v1 = *(const float4*)&qb[i * 8 + 4];
            ull k01 = pack2(k0.x, k0.y), k23 = pack2(k0.z, k0.w);
            ull k45 = pack2(k1.x, k1.y), k67 = pack2(k1.z, k1.w);
            ffma2(aA0, k01, pack2(u0.x, u0.y));
            ffma2(aA1, k23, pack2(u0.z, u0.w));
            ffma2(aA0, k45, pack2(u1.x, u1.y));
            ffma2(aA1, k67, pack2(u1.z, u1.w));
            ffma2(aB0, k01, pack2(v0.x, v0.y));
            ffma2(aB1, k23, pack2(v0.z, v0.w));
            ffma2(aB0, k45, pack2(v1.x, v1.y));
            ffma2(aB1, k67, pack2(v1.z, v1.w));
        }
        fadd2(aA0, aA1);
        fadd2(aB0, aB1);
        float2 fa = unpack2(aA0);
        float2 fb = unpack2(aB0);
        float s0 = fa.x + fa.y, s1 = fb.x + fb.y;

        float m0 = s0, m1 = s1;
#pragma unroll
        for (int o = 16; o > 0; o >>= 1) {
            m0 = fmaxf(m0, __shfl_xor_sync(0xffffffffu, m0, o));
            m1 = fmaxf(m1, __shfl_xor_sync(0xffffffffu, m1, o));
        }
        const int w = tid >> 5;
        if ((tid & 31) == 0) { red[w][0] = m0; red[w][1] = m1; }
        __syncthreads();
        const int wb = gh * 2;
        m0 = fmaxf(red[wb][0], red[wb + 1][0]);
        m1 = fmaxf(red[wb][1], red[wb + 1][1]);
        float e0 = __expf(s0 - m0);
        float e1 = __expf(s1 - m1);
        float q0 = e0, q1 = e1;
#pragma unroll
        for (int o = 16; o > 0; o >>= 1) {
            q0 += __shfl_xor_sync(0xffffffffu, q0, o);
            q1 += __shfl_xor_sync(0xffffffffu, q1, o);
        }
        __syncthreads();   // all done reading max partials
        if ((tid & 31) == 0) { red[w][0] = q0; red[w][1] = q1; }
        __syncthreads();
        float sum0 = red[wb][0] + red[wb + 1][0];
        float sum1 = red[wb][1] + red[wb + 1][1];
        ps[2 * gh][t]     = e0 * (1.0f / sum0);
        ps[2 * gh + 1][t] = e1 * (1.0f / sum1);
    }
    __syncthreads();

    // AV from registers: acc[g] over this thread's 8 t's, 4 channels
    {
        ull acc[4][2];
#pragma unroll
        for (int g = 0; g < 4; g++) { acc[g][0] = 0ULL; acc[g][1] = 0ULL; }
#pragma unroll
        for (int k = 0; k < 8; k++) {
            const int tt = sl + k * 8;
            ull k01 = pack2(kreg[k].x, kreg[k].y);
            ull k23 = pack2(kreg[k].z, kreg[k].w);
#pragma unroll
            for (int g = 0; g < 4; g++) {
                float pv = ps[g][tt];
                ull pp = pack2(pv, pv);
                ffma2(acc[g][0], pp, k01);
                ffma2(acc[g][1], pp, k23);
            }
        }
        // Pair-reduce across sl parity within the warp (lane ^ 16)
#pragma unroll
        for (int g = 0; g < 4; g++) {
#pragma unroll
            for (int h = 0; h < 2; h++) {
                ull o = __shfl_xor_sync(0xffffffffu, acc[g][h], 16);
                fadd2(acc[g][h], o);
            }
        }
        if ((tid & 16) == 0) {
            const int w = tid >> 5;   // slice index 0..3
#pragma unroll
            for (int g = 0; g < 4; g++) {
                float2 a = unpack2(acc[g][0]);
                float2 b = unpack2(acc[g][1]);
                float4 o; o.x = a.x; o.y = a.y; o.z = b.x; o.w = b.y;
                *(float4*)&wsp[w][g * 64 + f4 * 4] = o;
            }
        }
    }
    __syncthreads();

    // Reduce 4 slices, store w (float2 per thread)
    {
        const int o = tid * 2;
        float sx = 0.f, sy = 0.f;
#pragma unroll
        for (int slc = 0; slc < 4; slc++) {
            float2 v = *(const float2*)&wsp[slc][o];
            sx += v.x; sy += v.y;
        }
        float2 r; r.x = sx; r.y = sy;
        *(float2*)&g_w[(size_t)p * 256 + o] = r;
    }
}

// =====================================================================
// Kernel 3: x[p] = per-group w@Wv ; out[p] = x@Wout + b
// 256 blocks x 256 threads, 64 rows per block. 96KB smem -> 2 CTAs/SM.
// =====================================================================
__global__ void __launch_bounds__(256) out_kernel(const float* __restrict__ Wv,
                                                  const float* __restrict__ Wout,
                                                  const float* __restrict__ bias,
                                                  float* __restrict__ out) {
    extern __shared__ float sm[];
    float* sBig = sm;                 // [64][256]: w tile, then Wout
    float* sWv  = sm + 16384;         // [64][64]
    float* sX   = sm + 16384 + 4096;  // [64][64]
    const int tid = threadIdx.x;
    const int rowBase = blockIdx.x * 64;

    for (int i = tid; i < 1024; i += 256) ((float4*)sWv)[i] = ((const float4*)Wv)[i];
    {
        const float4* src = (const float4*)(g_w + (size_t)rowBase * 256);
        for (int i = tid; i < 4096; i += 256) ((float4*)sBig)[i] = src[i];
    }
    __syncthreads();

    // Phase 1: x[row][k] = sum_e w[row][g*64+e] * Wv[e][k], g = k>>4
    {
        const int tr = (tid >> 4) * 4;
        const int tc = (tid & 15) * 4;
        const int g  = tc >> 4;
        ull acc[4][2];
#pragma unroll
        for (int i = 0; i < 4; i++) { acc[i][0] = 0ULL; acc[i][1] = 0ULL; }
        for (int e = 0; e < 64; e++) {
            float4 wv = *(const float4*)&sWv[e * 64 + tc];
            ull w01 = pack2(wv.x, wv.y), w23 = pack2(wv.z, wv.w);
#pragma unroll
            for (int ri = 0; ri < 4; ri++) {
                float x = sBig[(tr + ri) * 256 + g * 64 + e];
                ull xx = pack2(x, x);
                ffma2(acc[ri][0], xx, w01);
                ffma2(acc[ri][1], xx, w23);
            }
        }
#pragma unroll
        for (int ri = 0; ri < 4; ri++) {
            float2 a = unpack2(acc[ri][0]);
            float2 b = unpack2(acc[ri][1]);
            float4 o; o.x = a.x; o.y = a.y; o.z = b.x; o.w = b.y;
            *(float4*)&sX[(tr + ri) * 64 + tc] = o;
        }
    }
    __syncthreads();

    // Reload sBig with Wout
    for (int i = tid; i < 4096; i += 256) ((float4*)sBig)[i] = ((const float4*)Wout)[i];
    __syncthreads();

    // Phase 2: out[row][d] = b[d] + sum_k x[row][k]*Wout[k][d]
    {
        const int rg = tid >> 6;
        const int c4 = tid & 63;
        ull acc[16][2];
#pragma unroll
        for (int i = 0; i < 16; i++) { acc[i][0] = 0ULL; acc[i][1] = 0ULL; }
        for (int k = 0; k < 64; k++) {
            float4 wd = *(const float4*)&sBig[k * 256 + c4 * 4];
            ull w01 = pack2(wd.x, wd.y), w23 = pack2(wd.z, wd.w);
            const float* xcol = &sX[rg * 16 * 64 + k];
#pragma unroll
            for (int rr = 0; rr < 16; rr++) {
                float xv = xcol[rr * 64];
                ull xx = pack2(xv, xv);
                ffma2(acc[rr][0], xx, w01);
                ffma2(acc[rr][1], xx, w23);
            }
        }
        float4 bv = ((const float4*)bias)[c4];
#pragma unroll
        for (int rr = 0; rr < 16; rr++) {
            float2 a = unpack2(acc[rr][0]);
            float2 b = unpack2(acc[rr][1]);
            float4 o;
            o.x = a.x + bv.x; o.y = a.y + bv.y;
            o.z = b.x + bv.z; o.w = b.y + bv.w;
            *(float4*)&out[(size_t)(rowBase + rg * 16 + rr) * 256 + c4 * 4] = o;
        }
    }
}

extern "C" void kernel_launch(void* const* d_in, const int* in_sizes, int n_in,
                              void* d_out, int out_size) {
    const float* q    = (const float*)d_in[0];
    const float* kv   = (const float*)d_in[1];
    const float* Wq   = (const float*)d_in[2];
    const float* Wk   = (const float*)d_in[3];
    const float* Wv   = (const float*)d_in[4];
    const float* Wout = (const float*)d_in[5];
    const float* bias = (const float*)d_in[6];
    float* out = (float*)d_out;

    cudaFuncSetAttribute(qk_kernel,  cudaFuncAttributeMaxDynamicSharedMemorySize, 49664);
    cudaFuncSetAttribute(out_kernel, cudaFuncAttributeMaxDynamicSharedMemorySize, 98304);

    qk_kernel<<<PTOT / 64, 256, 49664>>>(q, Wq, Wk);
    attn_kernel<<<PTOT, 128>>>(kv);
    out_kernel<<<PTOT / 64, 256, 98304>>>(Wv, Wout, bias, out);
}